// round 1
// baseline (speedup 1.0000x reference)
#include <cuda_runtime.h>

// LIF neuron: x is (N*T, F) with row index b = n*T + t, T=4, N=64, F=65536.
// Per (n,f): v=0; for t in 0..3: v = v*DECAY + x[n*T+t][f]; s=(v>=VTH); v-=s*VTH; out=s.
// Pure streaming problem -> aim for DRAM roofline with float4 loads/stores.

#define T_STEPS 4
#define DECAY 0.5f
#define VTH 1.0f

__global__ void lif_kernel(const float4* __restrict__ x, float4* __restrict__ out,
                           int fvec /* F/4 */)
{
    // Global vec4 index over (n, f4): total N * fvec
    long long idx = (long long)blockIdx.x * blockDim.x + threadIdx.x;
    // n = idx / fvec, f4 = idx % fvec ; rows for this n start at n*T_STEPS
    int n  = (int)(idx / fvec);
    int f4 = (int)(idx - (long long)n * fvec);

    long long base = ((long long)n * T_STEPS) * fvec + f4;

    // Front-batch the 4 loads (MLP=4) before any dependent math.
    float4 x0 = x[base];
    float4 x1 = x[base + fvec];
    float4 x2 = x[base + 2LL * fvec];
    float4 x3 = x[base + 3LL * fvec];

    float4 v = make_float4(0.f, 0.f, 0.f, 0.f);
    float4 s0, s1, s2, s3;

#define STEP(xt, st)                                                     \
    v.x = v.x * DECAY + (xt).x; (st).x = (v.x >= VTH) ? 1.f : 0.f; v.x -= (st).x * VTH; \
    v.y = v.y * DECAY + (xt).y; (st).y = (v.y >= VTH) ? 1.f : 0.f; v.y -= (st).y * VTH; \
    v.z = v.z * DECAY + (xt).z; (st).z = (v.z >= VTH) ? 1.f : 0.f; v.z -= (st).z * VTH; \
    v.w = v.w * DECAY + (xt).w; (st).w = (v.w >= VTH) ? 1.f : 0.f; v.w -= (st).w * VTH;

    STEP(x0, s0)
    STEP(x1, s1)
    STEP(x2, s2)
    STEP(x3, s3)
#undef STEP

    out[base]              = s0;
    out[base + fvec]       = s1;
    out[base + 2LL * fvec] = s2;
    out[base + 3LL * fvec] = s3;
}

extern "C" void kernel_launch(void* const* d_in, const int* in_sizes, int n_in,
                              void* d_out, int out_size)
{
    const float* x = (const float*)d_in[0];
    float* out = (float*)d_out;

    // x is (B, F) = (256, 65536); B = N*T with T=4.
    const int B = 256;
    const int F = 65536;
    const int N = B / T_STEPS;
    const int fvec = F / 4;

    long long total = (long long)N * fvec;          // 1,048,576 threads
    int threads = 256;
    int blocks = (int)((total + threads - 1) / threads);

    lif_kernel<<<blocks, threads>>>((const float4*)x, (float4*)out, fvec);
}